// round 14
// baseline (speedup 1.0000x reference)
#include <cuda_runtime.h>
#include <cuda_bf16.h>
#include <cuda_fp16.h>
#include <cstdint>

typedef unsigned long long ULL;

// ---------------- sm_80-class tensor path helpers ----------------
__device__ __forceinline__ uint32_t smem_u32(const void* p) {
    uint32_t a; asm("{ .reg .u64 t; cvta.to.shared.u64 t, %1; cvt.u32.u64 %0, t; }" : "=r"(a) : "l"(p));
    return a;
}
__device__ __forceinline__ void ldsm4(uint32_t* d, uint32_t a) {
    asm volatile("ldmatrix.sync.aligned.m8n8.x4.shared.b16 {%0,%1,%2,%3}, [%4];"
                 : "=r"(d[0]), "=r"(d[1]), "=r"(d[2]), "=r"(d[3]) : "r"(a));
}
__device__ __forceinline__ void ldsm4t(uint32_t* d, uint32_t a) {
    asm volatile("ldmatrix.sync.aligned.m8n8.x4.trans.shared.b16 {%0,%1,%2,%3}, [%4];"
                 : "=r"(d[0]), "=r"(d[1]), "=r"(d[2]), "=r"(d[3]) : "r"(a));
}
// D += A(m16k16,row) * B(k16n8,col), bf16 in, fp32 acc
__device__ __forceinline__ void mma16816(float* c, const uint32_t* a, uint32_t b0, uint32_t b1) {
    asm volatile("mma.sync.aligned.m16n8k16.row.col.f32.bf16.bf16.f32 "
                 "{%0,%1,%2,%3},{%4,%5,%6,%7},{%8,%9},{%0,%1,%2,%3};"
                 : "+f"(c[0]), "+f"(c[1]), "+f"(c[2]), "+f"(c[3])
                 : "r"(a[0]), "r"(a[1]), "r"(a[2]), "r"(a[3]), "r"(b0), "r"(b1));
}
// fp16 variant
__device__ __forceinline__ void mma16816h(float* c, const uint32_t* a, uint32_t b0, uint32_t b1) {
    asm volatile("mma.sync.aligned.m16n8k16.row.col.f32.f16.f16.f32 "
                 "{%0,%1,%2,%3},{%4,%5,%6,%7},{%8,%9},{%0,%1,%2,%3};"
                 : "+f"(c[0]), "+f"(c[1]), "+f"(c[2]), "+f"(c[3])
                 : "r"(a[0]), "r"(a[1]), "r"(a[2]), "r"(a[3]), "r"(b0), "r"(b1));
}
__device__ __forceinline__ void cpasync16(uint32_t s, const void* g) {
    asm volatile("cp.async.cg.shared.global [%0], [%1], 16;" :: "r"(s), "l"(g));
}
#define CP_COMMIT() asm volatile("cp.async.commit_group;" ::: "memory")
// pack two f32 -> bf16x2 / f16x2 (first arg in low half)
__device__ __forceinline__ uint32_t packbf2(float lo, float hi) {
    uint32_t r; asm("cvt.rn.bf16x2.f32 %0, %1, %2;" : "=r"(r) : "f"(hi), "f"(lo)); return r;
}
__device__ __forceinline__ uint32_t packhf2(float lo, float hi) {
    uint32_t r; asm("cvt.rn.f16x2.f32 %0, %1, %2;" : "=r"(r) : "f"(hi), "f"(lo)); return r;
}
__device__ __forceinline__ float lo_of(uint32_t u) { return __uint_as_float(u << 16); }
__device__ __forceinline__ float hi_of(uint32_t u) { return __uint_as_float(u & 0xFFFF0000u); }

#define SWZ(b) ((b) ^ (((b) >> 3) & 0x70))

// ---------------- scratch: Q/K/V single fp16; flat per-head [4096*64] ----------------
// Q is pre-scaled by 0.125 * log2(e) so flash can use exp2f (exact e^S).
__device__ __half g_q[16 * 262144];
__device__ __half g_k[16 * 262144];
__device__ __half g_v[16 * 262144];

// ==========================================================================
// Kernel 1: qkv GEMM via mma.sync bf16x3 (internal split, fp32-grade result).
// Epilogue: Q*=0.125*log2e -> fp16; K += pos emb -> fp16; V -> fp16.
// (unchanged from R12)
// ==========================================================================
static constexpr int QSM_WH = 0, QSM_WL = 16384, QSM_XH = 32768, QSM_XL = 40960;
static constexpr int QSM_TOT = 49152;

__global__ __launch_bounds__(256) void qkv_tc(const float* __restrict__ X,
                                              const float* __restrict__ W,
                                              const float* __restrict__ ph,
                                              const float* __restrict__ pw) {
    extern __shared__ __align__(1024) char qs[];
    const uint32_t sb = smem_u32(qs);
    const int tid = threadIdx.x, lane = tid & 31, warp = tid >> 5;
    const int s0 = blockIdx.x * 64;
    const int o0 = blockIdx.y * 128;
    const int b = blockIdx.z;

    float acc[4][2][4];
#pragma unroll
    for (int sc = 0; sc < 4; sc++)
#pragma unroll
        for (int nt = 0; nt < 2; nt++)
#pragma unroll
            for (int e = 0; e < 4; e++) acc[sc][nt][e] = 0.0f;

    const int rowF = (lane & 7) + (((lane >> 3) & 1) << 3);
    const int chkF = lane >> 4;

    for (int k0 = 0; k0 < 256; k0 += 64) {
#pragma unroll
        for (int rep = 0; rep < 8; rep++) {
            int idx = tid + rep * 256;
            int row = idx >> 4, c4 = idx & 15;
            float4 f = *(const float4*)(W + (size_t)(o0 + row) * 256 + k0 + c4 * 4);
            uint32_t h01 = packbf2(f.x, f.y), h23 = packbf2(f.z, f.w);
            uint32_t l01 = packbf2(f.x - lo_of(h01), f.y - hi_of(h01));
            uint32_t l23 = packbf2(f.z - lo_of(h23), f.w - hi_of(h23));
            uint32_t off = SWZ(row * 128 + c4 * 8);
            *(uint2*)(qs + QSM_WH + off) = make_uint2(h01, h23);
            *(uint2*)(qs + QSM_WL + off) = make_uint2(l01, l23);
        }
#pragma unroll
        for (int rep = 0; rep < 4; rep++) {
            int idx = tid + rep * 256;
            int row = idx >> 4, c4 = idx & 15;
            float4 f = *(const float4*)(X + ((size_t)b * 256 + k0 + row) * 4096 + s0 + c4 * 4);
            uint32_t h01 = packbf2(f.x, f.y), h23 = packbf2(f.z, f.w);
            uint32_t l01 = packbf2(f.x - lo_of(h01), f.y - hi_of(h01));
            uint32_t l23 = packbf2(f.z - lo_of(h23), f.w - hi_of(h23));
            uint32_t off = SWZ(row * 128 + c4 * 8);
            *(uint2*)(qs + QSM_XH + off) = make_uint2(h01, h23);
            *(uint2*)(qs + QSM_XL + off) = make_uint2(l01, l23);
        }
        __syncthreads();

#pragma unroll
        for (int kc = 0; kc < 4; kc++) {
            uint32_t awh[4], awl[4];
            uint32_t offA = SWZ((warp * 16 + rowF) * 128 + (2 * kc + chkF) * 16);
            ldsm4(awh, sb + QSM_WH + offA);
            ldsm4(awl, sb + QSM_WL + offA);
#pragma unroll
            for (int sc = 0; sc < 4; sc++) {
                uint32_t xh[4], xl[4];
                uint32_t offB = SWZ((16 * kc + rowF) * 128 + (2 * sc + chkF) * 16);
                ldsm4t(xh, sb + QSM_XH + offB);
                ldsm4t(xl, sb + QSM_XL + offB);
                mma16816(acc[sc][0], awh, xh[0], xh[1]);
                mma16816(acc[sc][0], awh, xl[0], xl[1]);
                mma16816(acc[sc][0], awl, xh[0], xh[1]);
                mma16816(acc[sc][1], awh, xh[2], xh[3]);
                mma16816(acc[sc][1], awh, xl[2], xl[3]);
                mma16816(acc[sc][1], awl, xh[2], xh[3]);
            }
        }
        __syncthreads();
    }

    // ---- epilogue ----
    const int r = lane >> 2, c2 = (lane & 3) * 2;
    const int bx = blockIdx.x;
    const float QSCALE = 0.125f * 1.44269504088896f;  // fold log2e for exp2f
#pragma unroll
    for (int half = 0; half < 2; half++) {
        int o_ch = o0 + warp * 16 + r + half * 8;
        int tensor = o_ch >> 8;
        int h = (o_ch >> 6) & 3;
        int ol = o_ch & 63;
        const size_t base = (size_t)(b * 4 + h) * 262144 + (size_t)ol * 4096 + s0;
        __half* g = tensor == 0 ? g_q : (tensor == 1 ? g_k : g_v);
#pragma unroll
        for (int sc = 0; sc < 4; sc++)
#pragma unroll
            for (int nt = 0; nt < 2; nt++) {
                int x = sc * 16 + nt * 8 + c2;
                float v0 = acc[sc][nt][half * 2 + 0];
                float v1 = acc[sc][nt][half * 2 + 1];
                if (tensor == 0) {
                    v0 *= QSCALE; v1 *= QSCALE;
                } else if (tensor == 1) {
                    v0 += ph[ol * 64 + x] + pw[bx * 64 + x];
                    v1 += ph[ol * 64 + x + 1] + pw[bx * 64 + x + 1];
                }
                *(uint32_t*)(g + base + x) = packhf2(v0, v1);
            }
    }
}

// ==========================================================================
// Kernel 2: flash attention, single-fp16, BM=256 (8 warps x 32 rows), BN=64.
// __launch_bounds__(256,1). R14: software-pipelined jc loop — QK MMAs for
// jc+1 are issued into a second accumulator bank BEFORE the exp burst of jc,
// so the tensor pipe drains QK(jc+1) while the warp sits in MUFU work.
// ==========================================================================
static constexpr int STAGE_BYTES = 16384;   // K 0..8K | V 8K..16K
static constexpr int SMEM_TOTAL = 2 * STAGE_BYTES;

__global__ __launch_bounds__(256, 1) void flash_attn(float* __restrict__ Out) {
    extern __shared__ __align__(1024) char smem[];
    const uint32_t sb = smem_u32(smem);
    const int tid = threadIdx.x, lane = tid & 31, warp = tid >> 5;
    const int bh = blockIdx.y;
    const int row0 = blockIdx.x * 256;
    const size_t hb = (size_t)bh * 262144;

    // ---- Q fragments for both row groups (g1 = g0 + 128 rows) ----
    const int r = lane >> 2, c2 = (lane & 3) * 2;
    uint32_t aq0[4][4], aq1[4][4];
    {
        const __half* q0 = g_q + hb + (size_t)(row0 + warp * 16 + r) * 64;
        const __half* q1 = q0 + (size_t)128 * 64;
#pragma unroll
        for (int ks = 0; ks < 4; ks++) {
            aq0[ks][0] = *(const uint32_t*)(q0 + ks * 16 + c2);
            aq0[ks][1] = *(const uint32_t*)(q0 + 8 * 64 + ks * 16 + c2);
            aq0[ks][2] = *(const uint32_t*)(q0 + ks * 16 + 8 + c2);
            aq0[ks][3] = *(const uint32_t*)(q0 + 8 * 64 + ks * 16 + 8 + c2);
            aq1[ks][0] = *(const uint32_t*)(q1 + ks * 16 + c2);
            aq1[ks][1] = *(const uint32_t*)(q1 + 8 * 64 + ks * 16 + c2);
            aq1[ks][2] = *(const uint32_t*)(q1 + ks * 16 + 8 + c2);
            aq1[ks][3] = *(const uint32_t*)(q1 + 8 * 64 + ks * 16 + 8 + c2);
        }
    }

    float o[16][4];   // [0..7]=group0 d-tiles, [8..15]=group1
#pragma unroll
    for (int t2 = 0; t2 < 16; t2++)
#pragma unroll
        for (int e = 0; e < 4; e++) o[t2][e] = 0.0f;
    float s0a = 0.0f, s0b = 0.0f, s1a = 0.0f, s1b = 0.0f;

    const int rowK = (lane & 7) + ((lane >> 4) << 3), chkK = (lane >> 3) & 1;   // non-trans (K)
    const int rowV = (lane & 7) + (((lane >> 3) & 1) << 3), chkV = (lane >> 4) & 1;  // trans (V)

    auto load_tile = [&](int kt, int stage) {
        uint32_t s = sb + stage * STAGE_BYTES;
        const size_t g0 = hb + (size_t)kt * 64 * 64;
#pragma unroll
        for (int rep = 0; rep < 2; rep++) {
            int c = tid + rep * 256;
            int row = c >> 3, col = c & 7;
            uint32_t soff = SWZ(row * 128 + col * 16);
            size_t g = g0 + (size_t)row * 64 + col * 8;
            cpasync16(s + soff, g_k + g);
            cpasync16(s + 8192 + soff, g_v + g);
        }
    };

    // QK tile for one jc into a given accumulator bank (c[4][4])
    auto compute_qk = [&](uint32_t sK, int jc, float (*c)[4]) {
#pragma unroll
        for (int ks = 0; ks < 4; ks++) {
            uint32_t kh[4];
            uint32_t off = SWZ((16 * jc + rowK) * 128 + (2 * ks + chkK) * 16);
            ldsm4(kh, sK + off);
            mma16816h(c[0], aq0[ks], kh[0], kh[1]);
            mma16816h(c[1], aq0[ks], kh[2], kh[3]);
            mma16816h(c[2], aq1[ks], kh[0], kh[1]);
            mma16816h(c[3], aq1[ks], kh[2], kh[3]);
        }
    };

    load_tile(0, 0);
    CP_COMMIT();

    for (int kt = 0; kt < 64; kt++) {
        if (kt < 63) { load_tile(kt + 1, (kt + 1) & 1); CP_COMMIT(); }
        if (kt < 63) { asm volatile("cp.async.wait_group 1;" ::: "memory"); }
        else         { asm volatile("cp.async.wait_group 0;" ::: "memory"); }
        __syncthreads();

        const uint32_t sK = sb + (kt & 1) * STAGE_BYTES;
        const uint32_t sV = sK + 8192;

        // double S-accumulator banks for the jc software pipeline
        float cb[2][4][4];
#pragma unroll
        for (int e = 0; e < 4; e++) {
            cb[0][0][e] = 0.0f; cb[0][1][e] = 0.0f; cb[0][2][e] = 0.0f; cb[0][3][e] = 0.0f;
        }
        compute_qk(sK, 0, cb[0]);   // prologue: S(0)

#pragma unroll
        for (int jj = 0; jj < 4; jj++) {
            const int cur = jj & 1;
            // issue QK(jj+1) into the other bank BEFORE the exp burst of jj —
            // these HMMAs drain on the tensor pipe while we do MUFU work.
            if (jj < 3) {
#pragma unroll
                for (int e = 0; e < 4; e++) {
                    cb[cur ^ 1][0][e] = 0.0f; cb[cur ^ 1][1][e] = 0.0f;
                    cb[cur ^ 1][2][e] = 0.0f; cb[cur ^ 1][3][e] = 0.0f;
                }
                compute_qk(sK, jj + 1, cb[cur ^ 1]);
            }

            // ---- exp2 on bank cur (Q pre-scaled by log2e; no max-sub) ----
            const float (*cc)[4] = cb[cur];
            float p0 = exp2f(cc[0][0]), p1 = exp2f(cc[0][1]), p2 = exp2f(cc[0][2]), p3 = exp2f(cc[0][3]);
            float p4 = exp2f(cc[1][0]), p5 = exp2f(cc[1][1]), p6 = exp2f(cc[1][2]), p7 = exp2f(cc[1][3]);
            s0a += (p0 + p1) + (p4 + p5);
            s0b += (p2 + p3) + (p6 + p7);
            uint32_t ap0[4];
            ap0[0] = packhf2(p0, p1);
            ap0[1] = packhf2(p2, p3);
            ap0[2] = packhf2(p4, p5);
            ap0[3] = packhf2(p6, p7);
            float q0e = exp2f(cc[2][0]), q1e = exp2f(cc[2][1]), q2e = exp2f(cc[2][2]), q3e = exp2f(cc[2][3]);
            float q4e = exp2f(cc[3][0]), q5e = exp2f(cc[3][1]), q6e = exp2f(cc[3][2]), q7e = exp2f(cc[3][3]);
            s1a += (q0e + q1e) + (q4e + q5e);
            s1b += (q2e + q3e) + (q6e + q7e);
            uint32_t ap1[4];
            ap1[0] = packhf2(q0e, q1e);
            ap1[1] = packhf2(q2e, q3e);
            ap1[2] = packhf2(q4e, q5e);
            ap1[3] = packhf2(q6e, q7e);

            // ---- O += P * V for jc=jj ----
#pragma unroll
            for (int dp = 0; dp < 4; dp++) {
                uint32_t vh[4];
                uint32_t off = SWZ((16 * jj + rowV) * 128 + (2 * dp + chkV) * 16);
                ldsm4t(vh, sV + off);
                mma16816h(o[2 * dp], ap0, vh[0], vh[1]);
                mma16816h(o[2 * dp + 1], ap0, vh[2], vh[3]);
                mma16816h(o[8 + 2 * dp], ap1, vh[0], vh[1]);
                mma16816h(o[8 + 2 * dp + 1], ap1, vh[2], vh[3]);
            }
        }
        __syncthreads();
    }

    // ---- reduce row sums across the 4 lanes sharing a row ----
    s0a += __shfl_xor_sync(0xffffffffu, s0a, 1);
    s0a += __shfl_xor_sync(0xffffffffu, s0a, 2);
    s0b += __shfl_xor_sync(0xffffffffu, s0b, 1);
    s0b += __shfl_xor_sync(0xffffffffu, s0b, 2);
    s1a += __shfl_xor_sync(0xffffffffu, s1a, 1);
    s1a += __shfl_xor_sync(0xffffffffu, s1a, 2);
    s1b += __shfl_xor_sync(0xffffffffu, s1b, 1);
    s1b += __shfl_xor_sync(0xffffffffu, s1b, 2);

    // ---- epilogue: raw-view output for both row groups ----
    float* Op = Out + (size_t)bh * 262144;
#pragma unroll
    for (int grp = 0; grp < 2; grp++) {
        const int i0 = row0 + grp * 128 + warp * 16 + r;
        const float inva = 1.0f / (grp == 0 ? s0a : s1a);
        const float invb = 1.0f / (grp == 0 ? s0b : s1b);
#pragma unroll
        for (int t2 = 0; t2 < 8; t2++) {
            const float* oc = o[grp * 8 + t2];
            float2 w0 = make_float2(oc[0] * inva, oc[1] * inva);
            float2 w1 = make_float2(oc[2] * invb, oc[3] * invb);
            *(float2*)(Op + (size_t)i0 * 64 + t2 * 8 + c2) = w0;
            *(float2*)(Op + (size_t)(i0 + 8) * 64 + t2 * 8 + c2) = w1;
        }
    }
}

// ==========================================================================
extern "C" void kernel_launch(void* const* d_in, const int* in_sizes, int n_in,
                              void* d_out, int out_size) {
    const float* fmap = (const float*)d_in[0];
    const float* w    = (const float*)d_in[1];
    const float* ph   = (const float*)d_in[2];
    const float* pw   = (const float*)d_in[3];
    float* out = (float*)d_out;

    cudaFuncSetAttribute(qkv_tc, cudaFuncAttributeMaxDynamicSharedMemorySize, QSM_TOT);
    cudaFuncSetAttribute(flash_attn, cudaFuncAttributeMaxDynamicSharedMemorySize, SMEM_TOTAL);
    qkv_tc<<<dim3(64, 6, 4), 256, QSM_TOT>>>(fmap, w, ph, pw);
    flash_attn<<<dim3(16, 16), 256, SMEM_TOTAL>>>(out);
}

// round 15
// speedup vs baseline: 1.0183x; 1.0183x over previous
#include <cuda_runtime.h>
#include <cuda_bf16.h>
#include <cuda_fp16.h>
#include <cstdint>

typedef unsigned long long ULL;

// ---------------- sm_80-class tensor path helpers ----------------
__device__ __forceinline__ uint32_t smem_u32(const void* p) {
    uint32_t a; asm("{ .reg .u64 t; cvta.to.shared.u64 t, %1; cvt.u32.u64 %0, t; }" : "=r"(a) : "l"(p));
    return a;
}
__device__ __forceinline__ void ldsm4(uint32_t* d, uint32_t a) {
    asm volatile("ldmatrix.sync.aligned.m8n8.x4.shared.b16 {%0,%1,%2,%3}, [%4];"
                 : "=r"(d[0]), "=r"(d[1]), "=r"(d[2]), "=r"(d[3]) : "r"(a));
}
__device__ __forceinline__ void ldsm4t(uint32_t* d, uint32_t a) {
    asm volatile("ldmatrix.sync.aligned.m8n8.x4.trans.shared.b16 {%0,%1,%2,%3}, [%4];"
                 : "=r"(d[0]), "=r"(d[1]), "=r"(d[2]), "=r"(d[3]) : "r"(a));
}
// D += A(m16k16,row) * B(k16n8,col), bf16 in, fp32 acc
__device__ __forceinline__ void mma16816(float* c, const uint32_t* a, uint32_t b0, uint32_t b1) {
    asm volatile("mma.sync.aligned.m16n8k16.row.col.f32.bf16.bf16.f32 "
                 "{%0,%1,%2,%3},{%4,%5,%6,%7},{%8,%9},{%0,%1,%2,%3};"
                 : "+f"(c[0]), "+f"(c[1]), "+f"(c[2]), "+f"(c[3])
                 : "r"(a[0]), "r"(a[1]), "r"(a[2]), "r"(a[3]), "r"(b0), "r"(b1));
}
// fp16 variant
__device__ __forceinline__ void mma16816h(float* c, const uint32_t* a, uint32_t b0, uint32_t b1) {
    asm volatile("mma.sync.aligned.m16n8k16.row.col.f32.f16.f16.f32 "
                 "{%0,%1,%2,%3},{%4,%5,%6,%7},{%8,%9},{%0,%1,%2,%3};"
                 : "+f"(c[0]), "+f"(c[1]), "+f"(c[2]), "+f"(c[3])
                 : "r"(a[0]), "r"(a[1]), "r"(a[2]), "r"(a[3]), "r"(b0), "r"(b1));
}
__device__ __forceinline__ void cpasync16(uint32_t s, const void* g) {
    asm volatile("cp.async.cg.shared.global [%0], [%1], 16;" :: "r"(s), "l"(g));
}
#define CP_COMMIT() asm volatile("cp.async.commit_group;" ::: "memory")
// pack two f32 -> bf16x2 / f16x2 (first arg in low half)
__device__ __forceinline__ uint32_t packbf2(float lo, float hi) {
    uint32_t r; asm("cvt.rn.bf16x2.f32 %0, %1, %2;" : "=r"(r) : "f"(hi), "f"(lo)); return r;
}
__device__ __forceinline__ uint32_t packhf2(float lo, float hi) {
    uint32_t r; asm("cvt.rn.f16x2.f32 %0, %1, %2;" : "=r"(r) : "f"(hi), "f"(lo)); return r;
}
__device__ __forceinline__ float lo_of(uint32_t u) { return __uint_as_float(u << 16); }
__device__ __forceinline__ float hi_of(uint32_t u) { return __uint_as_float(u & 0xFFFF0000u); }

#define SWZ(b) ((b) ^ (((b) >> 3) & 0x70))

// ---------------- scratch ----------------
// flash inputs: Q/K/V single fp16, flat per-head [4096*64]
// (Q pre-scaled by 0.125*log2e so flash uses exp2f)
__device__ __half g_q[16 * 262144];
__device__ __half g_k[16 * 262144];
__device__ __half g_v[16 * 262144];
// pre-converted GEMM inputs (bf16 hi/lo, flat row-major same as fp32 sources)
__device__ __nv_bfloat16 g_wh[768 * 256], g_wl[768 * 256];
__device__ __nv_bfloat16 g_xh[4 * 256 * 4096], g_xl[4 * 256 * 4096];

// ==========================================================================
// Kernel 0: one-time fp32 -> bf16 hi/lo conversion of W and X.
// Each element converted exactly ONCE (previously ~256x/6x inside qkv tiles).
// ==========================================================================
__global__ __launch_bounds__(256) void convert_wx(const float* __restrict__ X,
                                                  const float* __restrict__ W) {
    const int NW4 = (768 * 256) / 4;              // 49152
    const int NX4 = (4 * 256 * 4096) / 4;         // 1048576
    const int NTOT = NW4 + NX4;
    for (int i4 = blockIdx.x * blockDim.x + threadIdx.x; i4 < NTOT;
         i4 += gridDim.x * blockDim.x) {
        const bool isW = i4 < NW4;
        const int j4 = isW ? i4 : i4 - NW4;
        float4 f = isW ? ((const float4*)W)[j4] : ((const float4*)X)[j4];
        uint32_t h01 = packbf2(f.x, f.y), h23 = packbf2(f.z, f.w);
        uint32_t l01 = packbf2(f.x - lo_of(h01), f.y - hi_of(h01));
        uint32_t l23 = packbf2(f.z - lo_of(h23), f.w - hi_of(h23));
        if (isW) {
            ((uint2*)g_wh)[j4] = make_uint2(h01, h23);
            ((uint2*)g_wl)[j4] = make_uint2(l01, l23);
        } else {
            ((uint2*)g_xh)[j4] = make_uint2(h01, h23);
            ((uint2*)g_xl)[j4] = make_uint2(l01, l23);
        }
    }
}

// ==========================================================================
// Kernel 1: qkv GEMM via mma.sync bf16x3 — loads PRE-CONVERTED bf16 tiles
// via cp.async (no per-tile conversion). Epilogue unchanged:
// Q*=0.125*log2e -> fp16; K += pos emb -> fp16; V -> fp16.
// ==========================================================================
static constexpr int QSM_WH = 0, QSM_WL = 16384, QSM_XH = 32768, QSM_XL = 40960;
static constexpr int QSM_TOT = 49152;

__global__ __launch_bounds__(256) void qkv_tc(const float* __restrict__ ph,
                                              const float* __restrict__ pw) {
    extern __shared__ __align__(1024) char qs[];
    const uint32_t sb = smem_u32(qs);
    const int tid = threadIdx.x, lane = tid & 31, warp = tid >> 5;
    const int s0 = blockIdx.x * 64;
    const int o0 = blockIdx.y * 128;
    const int b = blockIdx.z;

    float acc[4][2][4];
#pragma unroll
    for (int sc = 0; sc < 4; sc++)
#pragma unroll
        for (int nt = 0; nt < 2; nt++)
#pragma unroll
            for (int e = 0; e < 4; e++) acc[sc][nt][e] = 0.0f;

    const int rowF = (lane & 7) + (((lane >> 3) & 1) << 3);
    const int chkF = lane >> 4;

    for (int k0 = 0; k0 < 256; k0 += 64) {
        // ---- W tiles (128 rows x 64 cols bf16, hi+lo): 8 chunks/row of 16B ----
#pragma unroll
        for (int rep = 0; rep < 4; rep++) {
            int idx = tid + rep * 256;
            int row = idx >> 3, ch = idx & 7;
            uint32_t soff = SWZ(row * 128 + ch * 16);
            size_t goff = (size_t)(o0 + row) * 256 + k0 + ch * 8;
            cpasync16(sb + QSM_WH + soff, g_wh + goff);
            cpasync16(sb + QSM_WL + soff, g_wl + goff);
        }
        // ---- X tiles (64 rows(k) x 64 cols(s) bf16, hi+lo) ----
#pragma unroll
        for (int rep = 0; rep < 2; rep++) {
            int idx = tid + rep * 256;
            int row = idx >> 3, ch = idx & 7;
            uint32_t soff = SWZ(row * 128 + ch * 16);
            size_t goff = ((size_t)b * 256 + k0 + row) * 4096 + s0 + ch * 8;
            cpasync16(sb + QSM_XH + soff, g_xh + goff);
            cpasync16(sb + QSM_XL + soff, g_xl + goff);
        }
        CP_COMMIT();
        asm volatile("cp.async.wait_group 0;" ::: "memory");
        __syncthreads();

#pragma unroll
        for (int kc = 0; kc < 4; kc++) {
            uint32_t awh[4], awl[4];
            uint32_t offA = SWZ((warp * 16 + rowF) * 128 + (2 * kc + chkF) * 16);
            ldsm4(awh, sb + QSM_WH + offA);
            ldsm4(awl, sb + QSM_WL + offA);
#pragma unroll
            for (int sc = 0; sc < 4; sc++) {
                uint32_t xh[4], xl[4];
                uint32_t offB = SWZ((16 * kc + rowF) * 128 + (2 * sc + chkF) * 16);
                ldsm4t(xh, sb + QSM_XH + offB);
                ldsm4t(xl, sb + QSM_XL + offB);
                mma16816(acc[sc][0], awh, xh[0], xh[1]);
                mma16816(acc[sc][0], awh, xl[0], xl[1]);
                mma16816(acc[sc][0], awl, xh[0], xh[1]);
                mma16816(acc[sc][1], awh, xh[2], xh[3]);
                mma16816(acc[sc][1], awh, xl[2], xl[3]);
                mma16816(acc[sc][1], awl, xh[2], xh[3]);
            }
        }
        __syncthreads();
    }

    // ---- epilogue (unchanged) ----
    const int r = lane >> 2, c2 = (lane & 3) * 2;
    const int bx = blockIdx.x;
    const float QSCALE = 0.125f * 1.44269504088896f;  // fold log2e for exp2f
#pragma unroll
    for (int half = 0; half < 2; half++) {
        int o_ch = o0 + warp * 16 + r + half * 8;
        int tensor = o_ch >> 8;
        int h = (o_ch >> 6) & 3;
        int ol = o_ch & 63;
        const size_t base = (size_t)(b * 4 + h) * 262144 + (size_t)ol * 4096 + s0;
        __half* g = tensor == 0 ? g_q : (tensor == 1 ? g_k : g_v);
#pragma unroll
        for (int sc = 0; sc < 4; sc++)
#pragma unroll
            for (int nt = 0; nt < 2; nt++) {
                int x = sc * 16 + nt * 8 + c2;
                float v0 = acc[sc][nt][half * 2 + 0];
                float v1 = acc[sc][nt][half * 2 + 1];
                if (tensor == 0) {
                    v0 *= QSCALE; v1 *= QSCALE;
                } else if (tensor == 1) {
                    v0 += ph[ol * 64 + x] + pw[bx * 64 + x];
                    v1 += ph[ol * 64 + x + 1] + pw[bx * 64 + x + 1];
                }
                *(uint32_t*)(g + base + x) = packhf2(v0, v1);
            }
    }
}

// ==========================================================================
// Kernel 2: flash attention (unchanged from R14 — 185.6us, tensor 61%).
// single-fp16, BM=256 (8 warps x 32 rows), BN=64, occ=1 (239 regs, no spill).
// ==========================================================================
static constexpr int STAGE_BYTES = 16384;   // K 0..8K | V 8K..16K
static constexpr int SMEM_TOTAL = 2 * STAGE_BYTES;

__global__ __launch_bounds__(256, 1) void flash_attn(float* __restrict__ Out) {
    extern __shared__ __align__(1024) char smem[];
    const uint32_t sb = smem_u32(smem);
    const int tid = threadIdx.x, lane = tid & 31, warp = tid >> 5;
    const int bh = blockIdx.y;
    const int row0 = blockIdx.x * 256;
    const size_t hb = (size_t)bh * 262144;

    // ---- Q fragments for both row groups (g1 = g0 + 128 rows) ----
    const int r = lane >> 2, c2 = (lane & 3) * 2;
    uint32_t aq0[4][4], aq1[4][4];
    {
        const __half* q0 = g_q + hb + (size_t)(row0 + warp * 16 + r) * 64;
        const __half* q1 = q0 + (size_t)128 * 64;
#pragma unroll
        for (int ks = 0; ks < 4; ks++) {
            aq0[ks][0] = *(const uint32_t*)(q0 + ks * 16 + c2);
            aq0[ks][1] = *(const uint32_t*)(q0 + 8 * 64 + ks * 16 + c2);
            aq0[ks][2] = *(const uint32_t*)(q0 + ks * 16 + 8 + c2);
            aq0[ks][3] = *(const uint32_t*)(q0 + 8 * 64 + ks * 16 + 8 + c2);
            aq1[ks][0] = *(const uint32_t*)(q1 + ks * 16 + c2);
            aq1[ks][1] = *(const uint32_t*)(q1 + 8 * 64 + ks * 16 + c2);
            aq1[ks][2] = *(const uint32_t*)(q1 + ks * 16 + 8 + c2);
            aq1[ks][3] = *(const uint32_t*)(q1 + 8 * 64 + ks * 16 + 8 + c2);
        }
    }

    float o[16][4];
#pragma unroll
    for (int t2 = 0; t2 < 16; t2++)
#pragma unroll
        for (int e = 0; e < 4; e++) o[t2][e] = 0.0f;
    float s0a = 0.0f, s0b = 0.0f, s1a = 0.0f, s1b = 0.0f;

    const int rowK = (lane & 7) + ((lane >> 4) << 3), chkK = (lane >> 3) & 1;
    const int rowV = (lane & 7) + (((lane >> 3) & 1) << 3), chkV = (lane >> 4) & 1;

    auto load_tile = [&](int kt, int stage) {
        uint32_t s = sb + stage * STAGE_BYTES;
        const size_t g0 = hb + (size_t)kt * 64 * 64;
#pragma unroll
        for (int rep = 0; rep < 2; rep++) {
            int c = tid + rep * 256;
            int row = c >> 3, col = c & 7;
            uint32_t soff = SWZ(row * 128 + col * 16);
            size_t g = g0 + (size_t)row * 64 + col * 8;
            cpasync16(s + soff, g_k + g);
            cpasync16(s + 8192 + soff, g_v + g);
        }
    };

    auto compute_qk = [&](uint32_t sK, int jc, float (*c)[4]) {
#pragma unroll
        for (int ks = 0; ks < 4; ks++) {
            uint32_t kh[4];
            uint32_t off = SWZ((16 * jc + rowK) * 128 + (2 * ks + chkK) * 16);
            ldsm4(kh, sK + off);
            mma16816h(c[0], aq0[ks], kh[0], kh[1]);
            mma16816h(c[1], aq0[ks], kh[2], kh[3]);
            mma16816h(c[2], aq1[ks], kh[0], kh[1]);
            mma16816h(c[3], aq1[ks], kh[2], kh[3]);
        }
    };

    load_tile(0, 0);
    CP_COMMIT();

    for (int kt = 0; kt < 64; kt++) {
        if (kt < 63) { load_tile(kt + 1, (kt + 1) & 1); CP_COMMIT(); }
        if (kt < 63) { asm volatile("cp.async.wait_group 1;" ::: "memory"); }
        else         { asm volatile("cp.async.wait_group 0;" ::: "memory"); }
        __syncthreads();

        const uint32_t sK = sb + (kt & 1) * STAGE_BYTES;
        const uint32_t sV = sK + 8192;

        float cb[2][4][4];
#pragma unroll
        for (int e = 0; e < 4; e++) {
            cb[0][0][e] = 0.0f; cb[0][1][e] = 0.0f; cb[0][2][e] = 0.0f; cb[0][3][e] = 0.0f;
        }
        compute_qk(sK, 0, cb[0]);

#pragma unroll
        for (int jj = 0; jj < 4; jj++) {
            const int cur = jj & 1;
            if (jj < 3) {
#pragma unroll
                for (int e = 0; e < 4; e++) {
                    cb[cur ^ 1][0][e] = 0.0f; cb[cur ^ 1][1][e] = 0.0f;
                    cb[cur ^ 1][2][e] = 0.0f; cb[cur ^ 1][3][e] = 0.0f;
                }
                compute_qk(sK, jj + 1, cb[cur ^ 1]);
            }

            const float (*cc)[4] = cb[cur];
            float p0 = exp2f(cc[0][0]), p1 = exp2f(cc[0][1]), p2 = exp2f(cc[0][2]), p3 = exp2f(cc[0][3]);
            float p4 = exp2f(cc[1][0]), p5 = exp2f(cc[1][1]), p6 = exp2f(cc[1][2]), p7 = exp2f(cc[1][3]);
            s0a += (p0 + p1) + (p4 + p5);
            s0b += (p2 + p3) + (p6 + p7);
            uint32_t ap0[4];
            ap0[0] = packhf2(p0, p1);
            ap0[1] = packhf2(p2, p3);
            ap0[2] = packhf2(p4, p5);
            ap0[3] = packhf2(p6, p7);
            float q0e = exp2f(cc[2][0]), q1e = exp2f(cc[2][1]), q2e = exp2f(cc[2][2]), q3e = exp2f(cc[2][3]);
            float q4e = exp2f(cc[3][0]), q5e = exp2f(cc[3][1]), q6e = exp2f(cc[3][2]), q7e = exp2f(cc[3][3]);
            s1a += (q0e + q1e) + (q4e + q5e);
            s1b += (q2e + q3e) + (q6e + q7e);
            uint32_t ap1[4];
            ap1[0] = packhf2(q0e, q1e);
            ap1[1] = packhf2(q2e, q3e);
            ap1[2] = packhf2(q4e, q5e);
            ap1[3] = packhf2(q6e, q7e);

#pragma unroll
            for (int dp = 0; dp < 4; dp++) {
                uint32_t vh[4];
                uint32_t off = SWZ((16 * jj + rowV) * 128 + (2 * dp + chkV) * 16);
                ldsm4t(vh, sV + off);
                mma16816h(o[2 * dp], ap0, vh[0], vh[1]);
                mma16816h(o[2 * dp + 1], ap0, vh[2], vh[3]);
                mma16816h(o[8 + 2 * dp], ap1, vh[0], vh[1]);
                mma16816h(o[8 + 2 * dp + 1], ap1, vh[2], vh[3]);
            }
        }
        __syncthreads();
    }

    s0a += __shfl_xor_sync(0xffffffffu, s0a, 1);
    s0a += __shfl_xor_sync(0xffffffffu, s0a, 2);
    s0b += __shfl_xor_sync(0xffffffffu, s0b, 1);
    s0b += __shfl_xor_sync(0xffffffffu, s0b, 2);
    s1a += __shfl_xor_sync(0xffffffffu, s1a, 1);
    s1a += __shfl_xor_sync(0xffffffffu, s1a, 2);
    s1b += __shfl_xor_sync(0xffffffffu, s1b, 1);
    s1b += __shfl_xor_sync(0xffffffffu, s1b, 2);

    float* Op = Out + (size_t)bh * 262144;
#pragma unroll
    for (int grp = 0; grp < 2; grp++) {
        const int i0 = row0 + grp * 128 + warp * 16 + r;
        const float inva = 1.0f / (grp == 0 ? s0a : s1a);
        const float invb = 1.0f / (grp == 0 ? s0b : s1b);
#pragma unroll
        for (int t2 = 0; t2 < 8; t2++) {
            const float* oc = o[grp * 8 + t2];
            float2 w0 = make_float2(oc[0] * inva, oc[1] * inva);
            float2 w1 = make_float2(oc[2] * invb, oc[3] * invb);
            *(float2*)(Op + (size_t)i0 * 64 + t2 * 8 + c2) = w0;
            *(float2*)(Op + (size_t)(i0 + 8) * 64 + t2 * 8 + c2) = w1;
        }
    }
}

// ==========================================================================
extern "C" void kernel_launch(void* const* d_in, const int* in_sizes, int n_in,
                              void* d_out, int out_size) {
    const float* fmap = (const float*)d_in[0];
    const float* w    = (const float*)d_in[1];
    const float* ph   = (const float*)d_in[2];
    const float* pw   = (const float*)d_in[3];
    float* out = (float*)d_out;

    cudaFuncSetAttribute(qkv_tc, cudaFuncAttributeMaxDynamicSharedMemorySize, QSM_TOT);
    cudaFuncSetAttribute(flash_attn, cudaFuncAttributeMaxDynamicSharedMemorySize, SMEM_TOTAL);
    convert_wx<<<2048, 256>>>(fmap, w);
    qkv_tc<<<dim3(64, 6, 4), 256, QSM_TOT>>>(ph, pw);
    flash_attn<<<dim3(16, 16), 256, SMEM_TOTAL>>>(out);
}